// round 10
// baseline (speedup 1.0000x reference)
#include <cuda_runtime.h>
#include <cuda_bf16.h>
#include <math.h>

#define Bc 4
#define Tt 288
#define Vv 512
#define Cc 32
#define NT 128      // threads per block
#define VT 8        // v columns per block

// Single fused kernel. Block = (b, 8-v tile). Streams t with smem rings.
//
// Identity used: sum_c W2[o,c] * filter_t(x[c]) = filter_t(sum_c W2[o,c] x[c]),
// so the expert pooling is applied to y2 = W2*x instead of per-channel x,
// and the residual folds into y1 via W1' = W1 + I.
//
// smem (floats unless noted):
//   sw[2048]   : W' transposed [g][c][o], g0 = W1+I, g1 = W2
//   sfb[32]    : fusion bias
//   scoef[8]   : expert coefs ew_i/k_i
//   simp[288]  : impact sum per t
//   sx[256]    : x[c=0..31][v=0..7] staging for current t (aliased as MLP h)
//   scv[2304]  : cv[t][v]  (prologue: events staging in first 864)
//   sy1[8192]  : y1 ring, 32 slots x 256   (prologue: flow staging 2304)
//   sy2 bf16[16384] : y2 ring, 64 slots x 256
__global__ void __launch_bounds__(128) kF(
    const float* __restrict__ x, const float* __restrict__ flow,
    const float* __restrict__ events, const float* __restrict__ ef,
    const float* __restrict__ w1, const float* __restrict__ b1,
    const float* __restrict__ w2, const float* __restrict__ b2,
    const float* __restrict__ fw, const float* __restrict__ fb,
    float* __restrict__ out)
{
    extern __shared__ __align__(16) float sm[];
    float* sw    = sm;              // 2048
    float* sfb   = sw + 2048;       // 32
    float* scoef = sfb + 32;        // 8
    float* simp  = scoef + 8;       // 288
    float* sx    = simp + 288;      // 256
    float* scv   = sx + 256;        // 2304
    float* sy1   = scv + 2304;      // 8192
    __nv_bfloat16* sy2 = (__nv_bfloat16*)(sy1 + 8192);   // 16384 bf16
    unsigned int* sy2u = (unsigned int*)sy2;
    float* sh    = sx;              // MLP hidden reuse (prologue only)
    float* sflow = sy1;             // flow staging reuse (prologue only)

    int tid = threadIdx.x;
    int v0  = blockIdx.x * VT;
    int b   = blockIdx.y;

    // ---- Phase A: weights (+identity fold), fb, events, zero impact ----
    for (int i = tid; i < 2048; i += NT) {
        int g = i >> 10, r = i & 1023, c = r >> 5, o = r & 31;
        float w = fw[o * 64 + g * 32 + c];
        if (g == 0 && o == c) w += 1.f;
        sw[i] = w;
    }
    if (tid < 32) sfb[tid] = fb[tid];
    for (int i = tid; i < Tt * 3; i += NT) scv[i] = events[b * Tt * 3 + i];
    for (int i = tid; i < Tt; i += NT) simp[i] = 0.f;
    __syncthreads();

    // ---- Phase B: impact scan (thr 0-2) | MLP hidden (thr 32-63) |
    //               flow staging + y2 ring zero (thr 64-127) ----
    if (tid < 3) {
        const float decay[3] = {300.f, 600.f, 180.f};
        const float alpha[3] = {0.3f, 0.5f, 0.2f};
        float r = expf(-1.f / decay[tid]);
        float a = alpha[tid];
        float s = 0.f;
        for (int t = Tt - 1; t >= 0; --t) {
            s = scv[t * 3 + tid] + r * s;
            atomicAdd(&simp[t], a * s);
        }
    } else if (tid >= 32 && tid < 64) {
        int j = tid - 32;
        float acc = b1[j];
#pragma unroll
        for (int i = 0; i < 8; ++i) acc += ef[b * 8 + i] * w1[i * 32 + j];
        sh[j] = fmaxf(acc, 0.f);
    } else if (tid >= 64) {
        for (int i = tid - 64; i < Tt * VT; i += 64) {
            int t = i >> 3, v = i & 7;
            sflow[i] = flow[(size_t)(b * Tt + t) * Vv + v0 + v];
        }
        for (int i = tid - 64; i < 8192; i += 64) sy2u[i] = 0u;
    }
    __syncthreads();

    // ---- Phase C: coefs (thr 32) + rolling CV (all threads) ----
    if (tid == 32) {
        float lg[5];
#pragma unroll
        for (int k = 0; k < 5; ++k) {
            float acc = b2[k];
#pragma unroll
            for (int j = 0; j < 32; ++j) acc += sh[j] * w2[j * 5 + k];
            lg[k] = 1.f / (1.f + expf(-acc));
        }
        float m = fmaxf(fmaxf(fmaxf(lg[0], lg[1]), fmaxf(lg[2], lg[3])), lg[4]);
        float ex[5], ssum = 0.f;
#pragma unroll
        for (int k = 0; k < 5; ++k) { ex[k] = expf(lg[k] - m); ssum += ex[k]; }
        const float ks[5] = {3.f, 6.f, 12.f, 24.f, 48.f};
#pragma unroll
        for (int k = 0; k < 5; ++k) scoef[k] = ex[k] / (ssum * ks[k]);
    }
    {   // cv: 16 chunks x 18 t, 8 v  (validated k_cv recurrence)
        int v = tid & 7, ch = tid >> 3;
        int ts = ch * 18;
        float s = 0.f, s2 = 0.f;
        int j0 = ts - 60; if (j0 < 0) j0 = 0;
        for (int j = j0; j < ts; ++j) {
            float f = sflow[j * 8 + v];
            s += f; s2 += f * f;
        }
        for (int t = ts; t < ts + 18; ++t) {
            float f = sflow[t * 8 + v];
            s += f; s2 += f * f;
            if (t >= 60) {
                float fo2 = sflow[(t - 60) * 8 + v];
                s -= fo2; s2 -= fo2 * fo2;
            }
            float c = 0.f;
            if (t >= 59) {
                float mean = s * (1.f / 60.f);
                float var = (s2 - 60.f * mean * mean) * (1.f / 59.f);
                var = fmaxf(var, 0.f);
                c = sqrtf(var) / (mean + 1e-6f);
            }
            scv[t * 8 + v] = c;
        }
    }
    __syncthreads();

    // ---- Main streaming loop ----
    int xc  = tid >> 2;             // 0..31 : channel for x staging
    int xvp = (tid & 3) * 2;        // v pair
    const float* xbase = x + ((size_t)(b * Cc + xc) * Tt) * Vv + v0 + xvp;
    float2 xreg = *(const float2*)xbase;   // t = 0

    int g  = tid >> 6;              // gemm id (0: y1', 1: y2)
    int og = (tid >> 3) & 7;        // o quad
    int vg = tid & 7;               // v
    const float* swg = sw + g * 1024;
    int o4 = og * 4;

    int fo  = tid >> 2;             // filter o (0..31)
    int fvp = tid & 3;              // filter v-pair (0..3)
    float c0 = scoef[0], c1 = scoef[1], c2 = scoef[2], c3 = scoef[3],
          c4 = scoef[4];

    float2 S0 = make_float2(0.f, 0.f), S1 = S0, S2 = S0, S3 = S0, S4 = S0;

    for (int t = 0; t < Tt + 23; ++t) {
        if (t < Tt) *(float2*)(sx + xc * 8 + xvp) = xreg;
        __syncthreads();
        if (t + 1 < Tt) xreg = *(const float2*)(xbase + (size_t)(t + 1) * Vv);

        if (t < Tt) {
            float a0 = 0.f, a1 = 0.f, a2 = 0.f, a3 = 0.f;
#pragma unroll
            for (int c = 0; c < 32; ++c) {
                float xv = sx[c * 8 + vg];
                float4 w = *(const float4*)(swg + c * 32 + o4);
                a0 += w.x * xv; a1 += w.y * xv;
                a2 += w.z * xv; a3 += w.w * xv;
            }
            if (g == 0) {
                float* yp = sy1 + (t & 31) * 256 + o4 * 8 + vg;
                yp[0]  = a0 + sfb[o4];
                yp[8]  = a1 + sfb[o4 + 1];
                yp[16] = a2 + sfb[o4 + 2];
                yp[24] = a3 + sfb[o4 + 3];
            } else {
                __nv_bfloat16* yp = sy2 + (t & 63) * 256 + o4 * 8 + vg;
                yp[0]  = __float2bfloat16(a0);
                yp[8]  = __float2bfloat16(a1);
                yp[16] = __float2bfloat16(a2);
                yp[24] = __float2bfloat16(a3);
            }
        } else if (g == 1) {
            __nv_bfloat16* yp = sy2 + (t & 63) * 256 + o4 * 8 + vg;
            __nv_bfloat16 z = __float2bfloat16(0.f);
            yp[0] = z; yp[8] = z; yp[16] = z; yp[24] = z;
        }
        __syncthreads();

        // sliding windows on y2 (validated k1 recurrence, pre-history = 0)
        {
            float2 zin = __bfloat1622float2(
                *(__nv_bfloat162*)&sy2u[(t & 63) * 128 + tid]);
            float2 a3v = __bfloat1622float2(
                *(__nv_bfloat162*)&sy2u[((t - 22) & 63) * 128 + tid]);
            float2 a6v = __bfloat1622float2(
                *(__nv_bfloat162*)&sy2u[((t - 21) & 63) * 128 + tid]);
            float2 a12v = __bfloat1622float2(
                *(__nv_bfloat162*)&sy2u[((t - 18) & 63) * 128 + tid]);
            float2 a24v = __bfloat1622float2(
                *(__nv_bfloat162*)&sy2u[((t - 12) & 63) * 128 + tid]);
            float2 d3v = __bfloat1622float2(
                *(__nv_bfloat162*)&sy2u[((t - 25) & 63) * 128 + tid]);
            float2 d6v = __bfloat1622float2(
                *(__nv_bfloat162*)&sy2u[((t - 27) & 63) * 128 + tid]);
            float2 d12v = __bfloat1622float2(
                *(__nv_bfloat162*)&sy2u[((t - 30) & 63) * 128 + tid]);
            float2 d24v = __bfloat1622float2(
                *(__nv_bfloat162*)&sy2u[((t - 36) & 63) * 128 + tid]);
            float2 d48v = __bfloat1622float2(
                *(__nv_bfloat162*)&sy2u[((t - 48) & 63) * 128 + tid]);

            S0.x += a3v.x  - d3v.x;   S0.y += a3v.y  - d3v.y;
            S1.x += a6v.x  - d6v.x;   S1.y += a6v.y  - d6v.y;
            S2.x += a12v.x - d12v.x;  S2.y += a12v.y - d12v.y;
            S3.x += a24v.x - d24v.x;  S3.y += a24v.y - d24v.y;
            S4.x += zin.x  - d48v.x;  S4.y += zin.y  - d48v.y;
        }

        int to = t - 23;
        if (to >= 0) {
            float2 y1v = *(float2*)(sy1 + (to & 31) * 256 + fo * 8 + fvp * 2);
            float2 cvv = *(float2*)(scv + to * 8 + fvp * 2);
            float impv = simp[to];
            float ox = (y1v.x + c0 * S0.x + c1 * S1.x + c2 * S2.x +
                        c3 * S3.x + c4 * S4.x) * (1.f + cvv.x) + impv;
            float oy = (y1v.y + c0 * S0.y + c1 * S1.y + c2 * S2.y +
                        c3 * S3.y + c4 * S4.y) * (1.f + cvv.y) + impv;
            *(float2*)(out + ((size_t)(b * Cc + fo) * Tt + to) * Vv +
                       v0 + fvp * 2) = make_float2(ox, oy);
        }
    }
}

// ---------------------------------------------------------------------------
extern "C" void kernel_launch(void* const* d_in, const int* in_sizes, int n_in,
                              void* d_out, int out_size) {
    const float* flow   = (const float*)d_in[0];
    const float* events = (const float*)d_in[1];
    const float* x      = (const float*)d_in[2];
    const float* ef     = (const float*)d_in[3];
    const float* w1     = (const float*)d_in[4];
    const float* b1     = (const float*)d_in[5];
    const float* w2     = (const float*)d_in[6];
    const float* b2     = (const float*)d_in[7];
    const float* fw     = (const float*)d_in[8];
    const float* fb     = (const float*)d_in[9];
    float* out = (float*)d_out;

    // floats: 2048+32+8+288+256+2304+8192 = 13128; + 16384 bf16
    const int smem_bytes = 13128 * 4 + 16384 * 2;   // 85280
    static bool attr_done = false;
    if (!attr_done) {
        cudaFuncSetAttribute(kF, cudaFuncAttributeMaxDynamicSharedMemorySize,
                             smem_bytes);
        attr_done = true;
    }

    kF<<<dim3(Vv / VT, Bc), NT, smem_bytes>>>(
        x, flow, events, ef, w1, b1, w2, b2, fw, fb, out);
}

// round 11
// speedup vs baseline: 1.5983x; 1.5983x over previous
#include <cuda_runtime.h>
#include <cuda_bf16.h>
#include <math.h>

#define Bc 4
#define Tt 288
#define Vv 512
#define Cc 32

// scratch (static __device__ arrays: allowed, no runtime allocation)
__device__ __nv_bfloat162 g_comb[Bc * Cc * Tt * (Vv / 2)];   // 37.7 MB
__device__ float g_cv[Bc * Tt * Vv];                          // 2.36 MB
__device__ float g_imp[Bc * Tt];

// ---------------------------------------------------------------------------
// kM: merged front kernel.
//   blocks [0, 1024)    : expert filter (k1f recurrence, 4-way t-split of 72
//                         outputs each, 49-step warm-up from zeroed ring —
//                         scheme validated in R8), coefs computed inline.
//   blocks [1024, 1088) : rolling CV (validated recurrence), 128 threads.
//   block  1088         : impact scan (validated).
// Dynamic smem: 64 KB (float2 ring for k1 role; cv/k0 roles use a slice).
// ---------------------------------------------------------------------------
__global__ void __launch_bounds__(128) kM(
    const float* __restrict__ xf, const float* __restrict__ flow,
    const float* __restrict__ events, const float* __restrict__ ef,
    const float* __restrict__ w1, const float* __restrict__ b1,
    const float* __restrict__ w2, const float* __restrict__ b2)
{
    extern __shared__ __align__(16) float dsm[];
    int tid = threadIdx.x;
    int bx = blockIdx.x;

    if (bx >= 1024) {
        if (bx < 1088) {
            // ---- rolling CV role ----
            float* sf = dsm;                    // 288*32 floats = 36 KB
            int idx = bx - 1024;                // 0..63
            int b  = idx >> 4;
            int v0 = (idx & 15) * 32;
            for (int i = tid; i < Tt * 32; i += 128) {
                int t = i >> 5, v = i & 31;
                sf[i] = flow[(size_t)(b * Tt + t) * Vv + v0 + v];
            }
            __syncthreads();
            int v = tid & 31;
            int ch = tid >> 5;                  // 0..3
            int ts = ch * 72;
            float s = 0.f, s2 = 0.f;
            int j0 = ts - 60; if (j0 < 0) j0 = 0;
            for (int j = j0; j < ts; ++j) {
                float f = sf[j * 32 + v];
                s += f; s2 += f * f;
            }
            float* cp = g_cv + (size_t)b * Tt * Vv + v0 + v;
#pragma unroll 4
            for (int t = ts; t < ts + 72; ++t) {
                float f = sf[t * 32 + v];
                s += f; s2 += f * f;
                if (t >= 60) {
                    float fo = sf[(t - 60) * 32 + v];
                    s -= fo; s2 -= fo * fo;
                }
                float c = 0.f;
                if (t >= 59) {
                    float mean = s * (1.f / 60.f);
                    float var = (s2 - 60.f * mean * mean) * (1.f / 59.f);
                    var = fmaxf(var, 0.f);
                    c = sqrtf(var) / (mean + 1e-6f);
                }
                cp[(size_t)t * Vv] = c;
            }
        } else {
            // ---- impact scan role ----
            float* sev  = dsm;                  // 3456
            float* part = dsm + Bc * Tt * 3;    // 3456
            for (int i = tid; i < Bc * Tt * 3; i += 128) sev[i] = events[i];
            __syncthreads();
            if (tid < 12) {
                int b = tid / 3, e = tid % 3;
                const float decay[3] = {300.f, 600.f, 180.f};
                const float alpha[3] = {0.3f, 0.5f, 0.2f};
                float r = expf(-1.f / decay[e]);
                float a = alpha[e];
                float s = 0.f;
                for (int t = Tt - 1; t >= 0; --t) {
                    s = sev[(b * Tt + t) * 3 + e] + r * s;
                    part[tid * Tt + t] = a * s;
                }
            }
            __syncthreads();
            for (int i = tid; i < Bc * Tt; i += 128) {
                int b = i / Tt, t = i - b * Tt;
                g_imp[i] = part[(b * 3 + 0) * Tt + t] +
                           part[(b * 3 + 1) * Tt + t] +
                           part[(b * 3 + 2) * Tt + t];
            }
        }
        return;
    }

    // ---- expert filter role (k1f, 4-way t-split) ----
    float2* rb2 = (float2*)dsm;                 // [64][128] = 64 KB
    __shared__ float sh[32];
    __shared__ float slg[5];
    __shared__ float scoef[5];

    int cb    = bx & 255;                       // column block 0..255
    int chunk = bx >> 8;                        // 0..3
    int ts    = chunk * 72;                     // outputs [ts, ts+72)
    int idx = cb * 128 + tid;                   // 0..32767 (b,c,vpair)
    int vp = idx & 255;
    int bc = idx >> 8;                          // constant per block = cb>>1
    int b  = bc >> 5;                           // constant per block

    // inline MLP -> sigmoid -> softmax -> coefs (b constant per block)
    if (tid < 32) {
        float acc = b1[tid];
#pragma unroll
        for (int i = 0; i < 8; ++i) acc += ef[b * 8 + i] * w1[i * 32 + tid];
        sh[tid] = fmaxf(acc, 0.f);
    }
    __syncthreads();
    if (tid < 5) {
        float acc = b2[tid];
#pragma unroll
        for (int j = 0; j < 32; ++j) acc += sh[j] * w2[j * 5 + tid];
        slg[tid] = 1.f / (1.f + expf(-acc));
    }
    __syncthreads();
    if (tid == 0) {
        float m = fmaxf(fmaxf(fmaxf(slg[0], slg[1]), fmaxf(slg[2], slg[3])),
                        slg[4]);
        float ex[5], ssum = 0.f;
#pragma unroll
        for (int k = 0; k < 5; ++k) { ex[k] = expf(slg[k] - m); ssum += ex[k]; }
        const float ks[5] = {3.f, 6.f, 12.f, 24.f, 48.f};
#pragma unroll
        for (int k = 0; k < 5; ++k) scoef[k] = ex[k] / (ssum * ks[k]);
    }

    const float2* xp = (const float2*)xf + (size_t)bc * Tt * 256 + vp;
    __nv_bfloat162* cp = g_comb + (size_t)bc * Tt * 256 + vp;

#pragma unroll
    for (int s = 0; s < 64; ++s) rb2[s * 128 + tid] = make_float2(0.f, 0.f);
    __syncthreads();

    float c0 = scoef[0], c1 = scoef[1], c2 = scoef[2], c3 = scoef[3],
          c4 = scoef[4];

    float2 S0 = make_float2(0.f, 0.f), S1 = S0, S2 = S0, S3 = S0, S4 = S0;

    float2 f[8];
#pragma unroll
    for (int j = 0; j < 8; ++j) {
        int tn = ts - 49 + j;
        f[j] = ((unsigned)tn < (unsigned)Tt)
                 ? __ldg(xp + (size_t)tn * 256) : make_float2(0.f, 0.f);
    }

    int tin = ts - 49;
    int tout0 = ts + 23;
    for (int g = 0; g < 18; ++g) {              // 18*8 = 144 steps
#pragma unroll
        for (int j = 0; j < 8; ++j) {
            float2 xin = f[j];
            float2 a3  = rb2[((tin - 22) & 63) * 128 + tid];
            float2 a6  = rb2[((tin - 21) & 63) * 128 + tid];
            float2 a12 = rb2[((tin - 18) & 63) * 128 + tid];
            float2 a24 = rb2[((tin - 12) & 63) * 128 + tid];
            float2 d3  = rb2[((tin - 25) & 63) * 128 + tid];
            float2 d6  = rb2[((tin - 27) & 63) * 128 + tid];
            float2 d12 = rb2[((tin - 30) & 63) * 128 + tid];
            float2 d24 = rb2[((tin - 36) & 63) * 128 + tid];
            float2 d48 = rb2[((tin - 48) & 63) * 128 + tid];

            S0.x += a3.x  - d3.x;   S0.y += a3.y  - d3.y;
            S1.x += a6.x  - d6.x;   S1.y += a6.y  - d6.y;
            S2.x += a12.x - d12.x;  S2.y += a12.y - d12.y;
            S3.x += a24.x - d24.x;  S3.y += a24.y - d24.y;
            S4.x += xin.x - d48.x;  S4.y += xin.y - d48.y;

            rb2[(tin & 63) * 128 + tid] = xin;

            if (tin >= tout0) {
                float ox = c0 * S0.x + c1 * S1.x + c2 * S2.x + c3 * S3.x +
                           c4 * S4.x;
                float oy = c0 * S0.y + c1 * S1.y + c2 * S2.y + c3 * S3.y +
                           c4 * S4.y;
                cp[(size_t)(tin - 23) * 256] = __floats2bfloat162_rn(ox, oy);
            }
            int tn = tin + 8;
            f[j] = ((unsigned)tn < (unsigned)Tt)
                     ? __ldg(xp + (size_t)tn * 256) : make_float2(0.f, 0.f);
            ++tin;
        }
    }
}

// ---------------------------------------------------------------------------
// K2 v5 (verbatim from R8, validated): fused channel mix + residual + CV +
// impact. Scalar FFMA, 4o x 4p, 256 thr, ~41 KB static smem.
// ---------------------------------------------------------------------------
__global__ void __launch_bounds__(256) k2s(const float* __restrict__ x,
                                           const float* __restrict__ fw,
                                           const float* __restrict__ fb,
                                           float* __restrict__ out) {
    __shared__ __align__(16) float s_cat[64 * 128];   // 32 KB [c][p]
    __shared__ __align__(16) float s_w[64 * 32];      // 8 KB  [c][o]
    __shared__ float s_cv[128];

    int tid = threadIdx.x;
    int v0 = blockIdx.x * 128;
    int t0 = blockIdx.y;
    int b  = blockIdx.z;

    const float4* x4 = reinterpret_cast<const float4*>(x);
    float4* cat4 = reinterpret_cast<float4*>(s_cat);
#pragma unroll
    for (int k = 0; k < 4; ++k) {
        int i = tid + k * 256;
        int c = i >> 5, r = i & 31;
        cat4[c * 32 + r] =
            x4[((b * Cc + c) * Tt + t0) * (Vv / 4) + (v0 >> 2) + r];
    }
    const uint2* m2 = reinterpret_cast<const uint2*>(g_comb);
#pragma unroll
    for (int k = 0; k < 4; ++k) {
        int i = tid + k * 256;
        int c = i >> 5, q = i & 31;
        uint2 u = __ldg(&m2[((b * Cc + c) * Tt + t0) * (Vv / 4) + (v0 >> 2) + q]);
        float2 lo = __bfloat1622float2(*reinterpret_cast<__nv_bfloat162*>(&u.x));
        float2 hi = __bfloat1622float2(*reinterpret_cast<__nv_bfloat162*>(&u.y));
        cat4[(32 + c) * 32 + q] = make_float4(lo.x, lo.y, hi.x, hi.y);
    }
#pragma unroll
    for (int k = 0; k < 8; ++k) {
        int i = tid + k * 256;
        int o = i >> 6, c = i & 63;
        s_w[c * 32 + o] = fw[i];
    }
    if (tid < 128) s_cv[tid] = g_cv[(size_t)(b * Tt + t0) * Vv + v0 + tid];
    __syncthreads();

    int og = tid >> 5;
    int pg = tid & 31;
    int p0 = pg << 2;

    float acc[16];
#pragma unroll
    for (int i = 0; i < 16; ++i) acc[i] = 0.f;

#pragma unroll 16
    for (int c = 0; c < 64; ++c) {
        float4 w  = *reinterpret_cast<const float4*>(&s_w[c * 32 + (og << 2)]);
        float4 xv = *reinterpret_cast<const float4*>(&s_cat[c * 128 + p0]);
        acc[0]  += w.x * xv.x;  acc[1]  += w.x * xv.y;
        acc[2]  += w.x * xv.z;  acc[3]  += w.x * xv.w;
        acc[4]  += w.y * xv.x;  acc[5]  += w.y * xv.y;
        acc[6]  += w.y * xv.z;  acc[7]  += w.y * xv.w;
        acc[8]  += w.z * xv.x;  acc[9]  += w.z * xv.y;
        acc[10] += w.z * xv.z;  acc[11] += w.z * xv.w;
        acc[12] += w.w * xv.x;  acc[13] += w.w * xv.y;
        acc[14] += w.w * xv.z;  acc[15] += w.w * xv.w;
    }

    float m0 = 1.f + s_cv[p0 + 0];
    float m1 = 1.f + s_cv[p0 + 1];
    float m2f = 1.f + s_cv[p0 + 2];
    float m3 = 1.f + s_cv[p0 + 3];
    float imp = __ldg(g_imp + b * Tt + t0);

#pragma unroll
    for (int oo = 0; oo < 4; ++oo) {
        int o = (og << 2) + oo;
        float fbv = __ldg(fb + o);
        float4 xres = *reinterpret_cast<const float4*>(&s_cat[o * 128 + p0]);
        float4 r;
        r.x = (acc[oo * 4 + 0] + fbv + xres.x) * m0  + imp;
        r.y = (acc[oo * 4 + 1] + fbv + xres.y) * m1  + imp;
        r.z = (acc[oo * 4 + 2] + fbv + xres.z) * m2f + imp;
        r.w = (acc[oo * 4 + 3] + fbv + xres.w) * m3  + imp;
        size_t oi = ((size_t)(b * Cc + o) * Tt + t0) * Vv + v0 + p0;
        *reinterpret_cast<float4*>(out + oi) = r;
    }
}

// ---------------------------------------------------------------------------
extern "C" void kernel_launch(void* const* d_in, const int* in_sizes, int n_in,
                              void* d_out, int out_size) {
    const float* flow   = (const float*)d_in[0];
    const float* events = (const float*)d_in[1];
    const float* x      = (const float*)d_in[2];
    const float* ef     = (const float*)d_in[3];
    const float* w1     = (const float*)d_in[4];
    const float* b1     = (const float*)d_in[5];
    const float* w2     = (const float*)d_in[6];
    const float* b2     = (const float*)d_in[7];
    const float* fw     = (const float*)d_in[8];
    const float* fb     = (const float*)d_in[9];
    float* out = (float*)d_out;

    const int smem_kM = 64 * 128 * sizeof(float2);   // 64 KB
    cudaFuncSetAttribute(kM, cudaFuncAttributeMaxDynamicSharedMemorySize,
                         smem_kM);

    kM<<<1089, 128, smem_kM>>>(x, flow, events, ef, w1, b1, w2, b2);
    k2s<<<dim3(Vv / 128, Tt, Bc), 256>>>(x, fw, fb, out);
}

// round 12
// speedup vs baseline: 1.6720x; 1.0461x over previous
#include <cuda_runtime.h>
#include <cuda_bf16.h>
#include <math.h>

#define Bc 4
#define Tt 288
#define Vv 512
#define Cc 32

// scratch (static __device__ arrays: allowed, no runtime allocation)
__device__ __nv_bfloat162 g_comb[Bc * Cc * Tt * (Vv / 2)];   // 37.7 MB
__device__ float g_cv[Bc * Tt * Vv];                          // 2.36 MB
__device__ float g_imp[Bc * Tt];

__device__ __forceinline__ unsigned packbf(float a, float b) {
    __nv_bfloat162 h = __floats2bfloat162_rn(a, b);   // .x = a (low half)
    return *reinterpret_cast<unsigned*>(&h);
}

// ---------------------------------------------------------------------------
// kM: merged front kernel (verbatim from R11, validated).
//   blocks [0,1024): expert filter (4-way t-split, 49-step zero-ring warm-up)
//   blocks [1024,1088): rolling CV    block 1088: impact scan
// ---------------------------------------------------------------------------
__global__ void __launch_bounds__(128) kM(
    const float* __restrict__ xf, const float* __restrict__ flow,
    const float* __restrict__ events, const float* __restrict__ ef,
    const float* __restrict__ w1, const float* __restrict__ b1,
    const float* __restrict__ w2, const float* __restrict__ b2)
{
    extern __shared__ __align__(16) float dsm[];
    int tid = threadIdx.x;
    int bx = blockIdx.x;

    if (bx >= 1024) {
        if (bx < 1088) {
            float* sf = dsm;
            int idx = bx - 1024;
            int b  = idx >> 4;
            int v0 = (idx & 15) * 32;
            for (int i = tid; i < Tt * 32; i += 128) {
                int t = i >> 5, v = i & 31;
                sf[i] = flow[(size_t)(b * Tt + t) * Vv + v0 + v];
            }
            __syncthreads();
            int v = tid & 31;
            int ch = tid >> 5;
            int ts = ch * 72;
            float s = 0.f, s2 = 0.f;
            int j0 = ts - 60; if (j0 < 0) j0 = 0;
            for (int j = j0; j < ts; ++j) {
                float f = sf[j * 32 + v];
                s += f; s2 += f * f;
            }
            float* cp = g_cv + (size_t)b * Tt * Vv + v0 + v;
#pragma unroll 4
            for (int t = ts; t < ts + 72; ++t) {
                float f = sf[t * 32 + v];
                s += f; s2 += f * f;
                if (t >= 60) {
                    float fo = sf[(t - 60) * 32 + v];
                    s -= fo; s2 -= fo * fo;
                }
                float c = 0.f;
                if (t >= 59) {
                    float mean = s * (1.f / 60.f);
                    float var = (s2 - 60.f * mean * mean) * (1.f / 59.f);
                    var = fmaxf(var, 0.f);
                    c = sqrtf(var) / (mean + 1e-6f);
                }
                cp[(size_t)t * Vv] = c;
            }
        } else {
            float* sev  = dsm;
            float* part = dsm + Bc * Tt * 3;
            for (int i = tid; i < Bc * Tt * 3; i += 128) sev[i] = events[i];
            __syncthreads();
            if (tid < 12) {
                int b = tid / 3, e = tid % 3;
                const float decay[3] = {300.f, 600.f, 180.f};
                const float alpha[3] = {0.3f, 0.5f, 0.2f};
                float r = expf(-1.f / decay[e]);
                float a = alpha[e];
                float s = 0.f;
                for (int t = Tt - 1; t >= 0; --t) {
                    s = sev[(b * Tt + t) * 3 + e] + r * s;
                    part[tid * Tt + t] = a * s;
                }
            }
            __syncthreads();
            for (int i = tid; i < Bc * Tt; i += 128) {
                int b = i / Tt, t = i - b * Tt;
                g_imp[i] = part[(b * 3 + 0) * Tt + t] +
                           part[(b * 3 + 1) * Tt + t] +
                           part[(b * 3 + 2) * Tt + t];
            }
        }
        return;
    }

    // ---- expert filter role ----
    float2* rb2 = (float2*)dsm;
    __shared__ float sh[32];
    __shared__ float slg[5];
    __shared__ float scoef[5];

    int cb    = bx & 255;
    int chunk = bx >> 8;
    int ts    = chunk * 72;
    int idx = cb * 128 + tid;
    int vp = idx & 255;
    int bc = idx >> 8;
    int b  = bc >> 5;

    if (tid < 32) {
        float acc = b1[tid];
#pragma unroll
        for (int i = 0; i < 8; ++i) acc += ef[b * 8 + i] * w1[i * 32 + tid];
        sh[tid] = fmaxf(acc, 0.f);
    }
    __syncthreads();
    if (tid < 5) {
        float acc = b2[tid];
#pragma unroll
        for (int j = 0; j < 32; ++j) acc += sh[j] * w2[j * 5 + tid];
        slg[tid] = 1.f / (1.f + expf(-acc));
    }
    __syncthreads();
    if (tid == 0) {
        float m = fmaxf(fmaxf(fmaxf(slg[0], slg[1]), fmaxf(slg[2], slg[3])),
                        slg[4]);
        float ex[5], ssum = 0.f;
#pragma unroll
        for (int k = 0; k < 5; ++k) { ex[k] = expf(slg[k] - m); ssum += ex[k]; }
        const float ks[5] = {3.f, 6.f, 12.f, 24.f, 48.f};
#pragma unroll
        for (int k = 0; k < 5; ++k) scoef[k] = ex[k] / (ssum * ks[k]);
    }

    const float2* xp = (const float2*)xf + (size_t)bc * Tt * 256 + vp;
    __nv_bfloat162* cp = g_comb + (size_t)bc * Tt * 256 + vp;

#pragma unroll
    for (int s = 0; s < 64; ++s) rb2[s * 128 + tid] = make_float2(0.f, 0.f);
    __syncthreads();

    float c0 = scoef[0], c1 = scoef[1], c2 = scoef[2], c3 = scoef[3],
          c4 = scoef[4];

    float2 S0 = make_float2(0.f, 0.f), S1 = S0, S2 = S0, S3 = S0, S4 = S0;

    float2 f[8];
#pragma unroll
    for (int j = 0; j < 8; ++j) {
        int tn = ts - 49 + j;
        f[j] = ((unsigned)tn < (unsigned)Tt)
                 ? __ldg(xp + (size_t)tn * 256) : make_float2(0.f, 0.f);
    }

    int tin = ts - 49;
    int tout0 = ts + 23;
    for (int g = 0; g < 18; ++g) {
#pragma unroll
        for (int j = 0; j < 8; ++j) {
            float2 xin = f[j];
            float2 a3  = rb2[((tin - 22) & 63) * 128 + tid];
            float2 a6  = rb2[((tin - 21) & 63) * 128 + tid];
            float2 a12 = rb2[((tin - 18) & 63) * 128 + tid];
            float2 a24 = rb2[((tin - 12) & 63) * 128 + tid];
            float2 d3  = rb2[((tin - 25) & 63) * 128 + tid];
            float2 d6  = rb2[((tin - 27) & 63) * 128 + tid];
            float2 d12 = rb2[((tin - 30) & 63) * 128 + tid];
            float2 d24 = rb2[((tin - 36) & 63) * 128 + tid];
            float2 d48 = rb2[((tin - 48) & 63) * 128 + tid];

            S0.x += a3.x  - d3.x;   S0.y += a3.y  - d3.y;
            S1.x += a6.x  - d6.x;   S1.y += a6.y  - d6.y;
            S2.x += a12.x - d12.x;  S2.y += a12.y - d12.y;
            S3.x += a24.x - d24.x;  S3.y += a24.y - d24.y;
            S4.x += xin.x - d48.x;  S4.y += xin.y - d48.y;

            rb2[(tin & 63) * 128 + tid] = xin;

            if (tin >= tout0) {
                float ox = c0 * S0.x + c1 * S1.x + c2 * S2.x + c3 * S3.x +
                           c4 * S4.x;
                float oy = c0 * S0.y + c1 * S1.y + c2 * S2.y + c3 * S3.y +
                           c4 * S4.y;
                cp[(size_t)(tin - 23) * 256] = __floats2bfloat162_rn(ox, oy);
            }
            int tn = tin + 8;
            f[j] = ((unsigned)tn < (unsigned)Tt)
                     ? __ldg(xp + (size_t)tn * 256) : make_float2(0.f, 0.f);
            ++tin;
        }
    }
}

// ---------------------------------------------------------------------------
// k2t: tensor-core channel mix. D[p=128][o=32] = cat^T[p,64] x W'[64,32],
// W' = fw^T + [I;0] (residual folded). bf16 mma.sync m16n8k16; A-frags via
// ldmatrix.x4.trans from bf16 cat [c][136-pad p]; B-frags built once from
// fp32 weights. Epilogue: (d + fb)*(1+cv) + imp, smem round-trip, STG.128.
// ---------------------------------------------------------------------------
__global__ void __launch_bounds__(256) k2t(const float* __restrict__ x,
                                           const float* __restrict__ fw,
                                           const float* __restrict__ fb,
                                           float* __restrict__ out) {
    __shared__ __align__(16) __nv_bfloat16 scat[64 * 136];   // 17408 B
    __shared__ __align__(16) float s_w[64 * 32];             // 8192 B
    __shared__ __align__(16) float s_out[32 * 132];          // 16896 B
    __shared__ float s_cv[128];
    __shared__ float sfb[32];

    int tid  = threadIdx.x;
    int lane = tid & 31;
    int warp = tid >> 5;
    int v0 = blockIdx.x * 128;
    int t0 = blockIdx.y;
    int b  = blockIdx.z;

    // fill x rows (fp32 -> bf16)
    const float4* x4 = reinterpret_cast<const float4*>(x);
#pragma unroll
    for (int k = 0; k < 4; ++k) {
        int i = tid + k * 256;            // 0..1023
        int c = i >> 5, q = i & 31;
        float4 v = x4[((b * Cc + c) * Tt + t0) * (Vv / 4) + (v0 >> 2) + q];
        unsigned lo = packbf(v.x, v.y);
        unsigned hi = packbf(v.z, v.w);
        *reinterpret_cast<uint2*>(&scat[c * 136 + q * 4]) = make_uint2(lo, hi);
    }
    // fill comb rows (already bf16 — raw copy)
    const uint2* m2 = reinterpret_cast<const uint2*>(g_comb);
#pragma unroll
    for (int k = 0; k < 4; ++k) {
        int i = tid + k * 256;
        int c = i >> 5, q = i & 31;
        uint2 u = __ldg(&m2[((b * Cc + c) * Tt + t0) * (Vv / 4) + (v0 >> 2) + q]);
        *reinterpret_cast<uint2*>(&scat[(32 + c) * 136 + q * 4]) = u;
    }
    // weights transposed [c][o] with identity fold (residual)
#pragma unroll
    for (int k = 0; k < 8; ++k) {
        int i = tid + k * 256;            // 0..2047
        int o = i >> 6, c = i & 63;
        float w = fw[o * 64 + c] + ((c == o) ? 1.f : 0.f);
        s_w[c * 32 + o] = w;
    }
    if (tid < 32) sfb[tid] = fb[tid];
    if (tid < 128) s_cv[tid] = g_cv[(size_t)(b * Tt + t0) * Vv + v0 + tid];
    __syncthreads();

    // B fragments (constant per block): b0 = W'[k..k+1][n], b1 = W'[k+8..k+9][n]
    int bn = lane >> 2;
    int bk = (lane & 3) * 2;
    unsigned bfr[4][4][2];
#pragma unroll
    for (int nt = 0; nt < 4; ++nt)
#pragma unroll
        for (int kc = 0; kc < 4; ++kc) {
            int n = nt * 8 + bn;
            int k0 = kc * 16 + bk;
            bfr[nt][kc][0] = packbf(s_w[k0 * 32 + n], s_w[(k0 + 1) * 32 + n]);
            bfr[nt][kc][1] = packbf(s_w[(k0 + 8) * 32 + n], s_w[(k0 + 9) * 32 + n]);
        }

    float acc[4][4];
#pragma unroll
    for (int nt = 0; nt < 4; ++nt)
#pragma unroll
        for (int i = 0; i < 4; ++i) acc[nt][i] = 0.f;

    // A fragments via ldmatrix.x4.trans; 16 mma per warp
    unsigned sbase = (unsigned)__cvta_generic_to_shared(scat);
    int p0w  = warp * 16;
    int tile = lane >> 3, r = lane & 7;
    int kofs = (tile >> 1) * 8 + r;       // c-row offset within k-chunk
    int pofs = p0w + (tile & 1) * 8;      // p offset
#pragma unroll
    for (int kc = 0; kc < 4; ++kc) {
        unsigned addr = sbase + (unsigned)(((kc * 16 + kofs) * 136 + pofs) * 2);
        unsigned a0, a1, a2, a3;
        asm volatile(
            "ldmatrix.sync.aligned.m8n8.x4.trans.shared.b16 {%0,%1,%2,%3}, [%4];"
            : "=r"(a0), "=r"(a1), "=r"(a2), "=r"(a3) : "r"(addr));
#pragma unroll
        for (int nt = 0; nt < 4; ++nt) {
            asm volatile(
                "mma.sync.aligned.m16n8k16.row.col.f32.bf16.bf16.f32 "
                "{%0,%1,%2,%3}, {%4,%5,%6,%7}, {%8,%9}, {%0,%1,%2,%3};"
                : "+f"(acc[nt][0]), "+f"(acc[nt][1]),
                  "+f"(acc[nt][2]), "+f"(acc[nt][3])
                : "r"(a0), "r"(a1), "r"(a2), "r"(a3),
                  "r"(bfr[nt][kc][0]), "r"(bfr[nt][kc][1]));
        }
    }

    // epilogue in-register, then smem round-trip for coalesced stores
    float imp = __ldg(g_imp + b * Tt + t0);
    int eo = (lane & 3) * 2;
    int ep = p0w + (lane >> 2);
    float m_lo = 1.f + s_cv[ep];
    float m_hi = 1.f + s_cv[ep + 8];
#pragma unroll
    for (int nt = 0; nt < 4; ++nt) {
        int o0 = nt * 8 + eo;
        float f0 = sfb[o0], f1 = sfb[o0 + 1];
        s_out[o0 * 132 + ep]            = (acc[nt][0] + f0) * m_lo + imp;
        s_out[(o0 + 1) * 132 + ep]      = (acc[nt][1] + f1) * m_lo + imp;
        s_out[o0 * 132 + ep + 8]        = (acc[nt][2] + f0) * m_hi + imp;
        s_out[(o0 + 1) * 132 + ep + 8]  = (acc[nt][3] + f1) * m_hi + imp;
    }
    __syncthreads();

#pragma unroll
    for (int k = 0; k < 4; ++k) {
        int i = tid + k * 256;            // 0..1023
        int o = i >> 5, pq = i & 31;
        float4 v = *reinterpret_cast<const float4*>(&s_out[o * 132 + pq * 4]);
        *reinterpret_cast<float4*>(
            &out[((size_t)(b * Cc + o) * Tt + t0) * Vv + v0 + pq * 4]) = v;
    }
}

// ---------------------------------------------------------------------------
extern "C" void kernel_launch(void* const* d_in, const int* in_sizes, int n_in,
                              void* d_out, int out_size) {
    const float* flow   = (const float*)d_in[0];
    const float* events = (const float*)d_in[1];
    const float* x      = (const float*)d_in[2];
    const float* ef     = (const float*)d_in[3];
    const float* w1     = (const float*)d_in[4];
    const float* b1     = (const float*)d_in[5];
    const float* w2     = (const float*)d_in[6];
    const float* b2     = (const float*)d_in[7];
    const float* fw     = (const float*)d_in[8];
    const float* fb     = (const float*)d_in[9];
    float* out = (float*)d_out;

    const int smem_kM = 64 * 128 * sizeof(float2);   // 64 KB
    cudaFuncSetAttribute(kM, cudaFuncAttributeMaxDynamicSharedMemorySize,
                         smem_kM);

    kM<<<1089, 128, smem_kM>>>(x, flow, events, ef, w1, b1, w2, b2);
    k2t<<<dim3(Vv / 128, Tt, Bc), 256>>>(x, fw, fb, out);
}

// round 13
// speedup vs baseline: 2.5607x; 1.5315x over previous
#include <cuda_runtime.h>
#include <cuda_bf16.h>
#include <math.h>

#define Bc 4
#define Tt 288
#define Vv 512
#define Cc 32

// scratch (static __device__ arrays: allowed, no runtime allocation)
__device__ __nv_bfloat162 g_comb[Bc * Cc * Tt * (Vv / 2)];   // 37.7 MB
__device__ float g_cv[Bc * Tt * Vv];                          // 2.36 MB
__device__ float g_imp[Bc * Tt];
__device__ unsigned g_bfrag[16 * 64];                         // 4 KB B-fragments

__device__ __forceinline__ unsigned packbf(float a, float b) {
    __nv_bfloat162 h = __floats2bfloat162_rn(a, b);   // .x = a (low half)
    return *reinterpret_cast<unsigned*>(&h);
}

// ---------------------------------------------------------------------------
// kM: merged front kernel.
//   blocks [0,1024): expert filter (validated R11)
//   blocks [1024,1088): rolling CV     block 1088: impact scan
//   block 1089: B-fragment table (W' = fw^T + I fold, packed bf16, laid out
//               exactly as mma consumes: g_bfrag[(nt*4+kc)*64 + lane*2 + j])
// ---------------------------------------------------------------------------
__global__ void __launch_bounds__(128) kM(
    const float* __restrict__ xf, const float* __restrict__ flow,
    const float* __restrict__ events, const float* __restrict__ ef,
    const float* __restrict__ w1, const float* __restrict__ b1,
    const float* __restrict__ w2, const float* __restrict__ b2,
    const float* __restrict__ fw)
{
    extern __shared__ __align__(16) float dsm[];
    int tid = threadIdx.x;
    int bx = blockIdx.x;

    if (bx >= 1024) {
        if (bx < 1088) {
            // ---- rolling CV role (validated) ----
            float* sf = dsm;
            int idx = bx - 1024;
            int b  = idx >> 4;
            int v0 = (idx & 15) * 32;
            for (int i = tid; i < Tt * 32; i += 128) {
                int t = i >> 5, v = i & 31;
                sf[i] = flow[(size_t)(b * Tt + t) * Vv + v0 + v];
            }
            __syncthreads();
            int v = tid & 31;
            int ch = tid >> 5;
            int ts = ch * 72;
            float s = 0.f, s2 = 0.f;
            int j0 = ts - 60; if (j0 < 0) j0 = 0;
            for (int j = j0; j < ts; ++j) {
                float f = sf[j * 32 + v];
                s += f; s2 += f * f;
            }
            float* cp = g_cv + (size_t)b * Tt * Vv + v0 + v;
#pragma unroll 4
            for (int t = ts; t < ts + 72; ++t) {
                float f = sf[t * 32 + v];
                s += f; s2 += f * f;
                if (t >= 60) {
                    float fo = sf[(t - 60) * 32 + v];
                    s -= fo; s2 -= fo * fo;
                }
                float c = 0.f;
                if (t >= 59) {
                    float mean = s * (1.f / 60.f);
                    float var = (s2 - 60.f * mean * mean) * (1.f / 59.f);
                    var = fmaxf(var, 0.f);
                    c = sqrtf(var) / (mean + 1e-6f);
                }
                cp[(size_t)t * Vv] = c;
            }
        } else if (bx == 1088) {
            // ---- impact scan role (validated) ----
            float* sev  = dsm;
            float* part = dsm + Bc * Tt * 3;
            for (int i = tid; i < Bc * Tt * 3; i += 128) sev[i] = events[i];
            __syncthreads();
            if (tid < 12) {
                int b = tid / 3, e = tid % 3;
                const float decay[3] = {300.f, 600.f, 180.f};
                const float alpha[3] = {0.3f, 0.5f, 0.2f};
                float r = expf(-1.f / decay[e]);
                float a = alpha[e];
                float s = 0.f;
                for (int t = Tt - 1; t >= 0; --t) {
                    s = sev[(b * Tt + t) * 3 + e] + r * s;
                    part[tid * Tt + t] = a * s;
                }
            }
            __syncthreads();
            for (int i = tid; i < Bc * Tt; i += 128) {
                int b = i / Tt, t = i - b * Tt;
                g_imp[i] = part[(b * 3 + 0) * Tt + t] +
                           part[(b * 3 + 1) * Tt + t] +
                           part[(b * 3 + 2) * Tt + t];
            }
        } else {
            // ---- B-fragment table role ----
            // W'[c][o] = fw[o*64+c] + (c==o). Fragment values identical to
            // R12's validated in-kernel build:
            //   j=0: pack(W'[k0][n],   W'[k0+1][n])
            //   j=1: pack(W'[k0+8][n], W'[k0+9][n])
            if (tid < 32) {
                int bn = tid >> 2, bk = (tid & 3) * 2;
#pragma unroll
                for (int nt = 0; nt < 4; ++nt)
#pragma unroll
                    for (int kc = 0; kc < 4; ++kc) {
                        int n = nt * 8 + bn;
                        int k0 = kc * 16 + bk;
                        float w00 = fw[n * 64 + k0]     + (k0     == n ? 1.f : 0.f);
                        float w01 = fw[n * 64 + k0 + 1] + (k0 + 1 == n ? 1.f : 0.f);
                        float w80 = fw[n * 64 + k0 + 8] + (k0 + 8 == n ? 1.f : 0.f);
                        float w81 = fw[n * 64 + k0 + 9] + (k0 + 9 == n ? 1.f : 0.f);
                        g_bfrag[(nt * 4 + kc) * 64 + tid * 2 + 0] = packbf(w00, w01);
                        g_bfrag[(nt * 4 + kc) * 64 + tid * 2 + 1] = packbf(w80, w81);
                    }
            }
        }
        return;
    }

    // ---- expert filter role (validated R11) ----
    float2* rb2 = (float2*)dsm;
    __shared__ float sh[32];
    __shared__ float slg[5];
    __shared__ float scoef[5];

    int cb    = bx & 255;
    int chunk = bx >> 8;
    int ts    = chunk * 72;
    int idx = cb * 128 + tid;
    int vp = idx & 255;
    int bc = idx >> 8;
    int b  = bc >> 5;

    if (tid < 32) {
        float acc = b1[tid];
#pragma unroll
        for (int i = 0; i < 8; ++i) acc += ef[b * 8 + i] * w1[i * 32 + tid];
        sh[tid] = fmaxf(acc, 0.f);
    }
    __syncthreads();
    if (tid < 5) {
        float acc = b2[tid];
#pragma unroll
        for (int j = 0; j < 32; ++j) acc += sh[j] * w2[j * 5 + tid];
        slg[tid] = 1.f / (1.f + expf(-acc));
    }
    __syncthreads();
    if (tid == 0) {
        float m = fmaxf(fmaxf(fmaxf(slg[0], slg[1]), fmaxf(slg[2], slg[3])),
                        slg[4]);
        float ex[5], ssum = 0.f;
#pragma unroll
        for (int k = 0; k < 5; ++k) { ex[k] = expf(slg[k] - m); ssum += ex[k]; }
        const float ks[5] = {3.f, 6.f, 12.f, 24.f, 48.f};
#pragma unroll
        for (int k = 0; k < 5; ++k) scoef[k] = ex[k] / (ssum * ks[k]);
    }

    const float2* xp = (const float2*)xf + (size_t)bc * Tt * 256 + vp;
    __nv_bfloat162* cp = g_comb + (size_t)bc * Tt * 256 + vp;

#pragma unroll
    for (int s = 0; s < 64; ++s) rb2[s * 128 + tid] = make_float2(0.f, 0.f);
    __syncthreads();

    float c0 = scoef[0], c1 = scoef[1], c2 = scoef[2], c3 = scoef[3],
          c4 = scoef[4];

    float2 S0 = make_float2(0.f, 0.f), S1 = S0, S2 = S0, S3 = S0, S4 = S0;

    float2 f[8];
#pragma unroll
    for (int j = 0; j < 8; ++j) {
        int tn = ts - 49 + j;
        f[j] = ((unsigned)tn < (unsigned)Tt)
                 ? __ldg(xp + (size_t)tn * 256) : make_float2(0.f, 0.f);
    }

    int tin = ts - 49;
    int tout0 = ts + 23;
    for (int g = 0; g < 18; ++g) {
#pragma unroll
        for (int j = 0; j < 8; ++j) {
            float2 xin = f[j];
            float2 a3  = rb2[((tin - 22) & 63) * 128 + tid];
            float2 a6  = rb2[((tin - 21) & 63) * 128 + tid];
            float2 a12 = rb2[((tin - 18) & 63) * 128 + tid];
            float2 a24 = rb2[((tin - 12) & 63) * 128 + tid];
            float2 d3  = rb2[((tin - 25) & 63) * 128 + tid];
            float2 d6  = rb2[((tin - 27) & 63) * 128 + tid];
            float2 d12 = rb2[((tin - 30) & 63) * 128 + tid];
            float2 d24 = rb2[((tin - 36) & 63) * 128 + tid];
            float2 d48 = rb2[((tin - 48) & 63) * 128 + tid];

            S0.x += a3.x  - d3.x;   S0.y += a3.y  - d3.y;
            S1.x += a6.x  - d6.x;   S1.y += a6.y  - d6.y;
            S2.x += a12.x - d12.x;  S2.y += a12.y - d12.y;
            S3.x += a24.x - d24.x;  S3.y += a24.y - d24.y;
            S4.x += xin.x - d48.x;  S4.y += xin.y - d48.y;

            rb2[(tin & 63) * 128 + tid] = xin;

            if (tin >= tout0) {
                float ox = c0 * S0.x + c1 * S1.x + c2 * S2.x + c3 * S3.x +
                           c4 * S4.x;
                float oy = c0 * S0.y + c1 * S1.y + c2 * S2.y + c3 * S3.y +
                           c4 * S4.y;
                cp[(size_t)(tin - 23) * 256] = __floats2bfloat162_rn(ox, oy);
            }
            int tn = tin + 8;
            f[j] = ((unsigned)tn < (unsigned)Tt)
                     ? __ldg(xp + (size_t)tn * 256) : make_float2(0.f, 0.f);
            ++tin;
        }
    }
}

// ---------------------------------------------------------------------------
// k2t v2: tensor-core channel mix. Same validated MMA structure as R12, but
// B-fragments come from the precomputed g_bfrag table: one uint4 LDG per
// thread to stage 4 KB into smem, then one conflict-free LDS.64 per mma
// (replaces 64 scalar LDS + 32 packbf per thread + 2 KB s_w staging).
// ---------------------------------------------------------------------------
__global__ void __launch_bounds__(256) k2t(const float* __restrict__ x,
                                           const float* __restrict__ fb,
                                           float* __restrict__ out) {
    __shared__ __align__(16) __nv_bfloat16 scat[64 * 136];   // 17408 B
    __shared__ __align__(16) float s_out[32 * 132];          // 16896 B
    __shared__ __align__(16) unsigned s_bf[16 * 64];         // 4096 B
    __shared__ float s_cv[128];
    __shared__ float sfb[32];

    int tid  = threadIdx.x;
    int lane = tid & 31;
    int warp = tid >> 5;
    int v0 = blockIdx.x * 128;
    int t0 = blockIdx.y;
    int b  = blockIdx.z;

    // fill x rows (fp32 -> bf16)
    const float4* x4 = reinterpret_cast<const float4*>(x);
#pragma unroll
    for (int k = 0; k < 4; ++k) {
        int i = tid + k * 256;            // 0..1023
        int c = i >> 5, q = i & 31;
        float4 v = x4[((b * Cc + c) * Tt + t0) * (Vv / 4) + (v0 >> 2) + q];
        unsigned lo = packbf(v.x, v.y);
        unsigned hi = packbf(v.z, v.w);
        *reinterpret_cast<uint2*>(&scat[c * 136 + q * 4]) = make_uint2(lo, hi);
    }
    // fill comb rows (already bf16 — raw copy)
    const uint2* m2 = reinterpret_cast<const uint2*>(g_comb);
#pragma unroll
    for (int k = 0; k < 4; ++k) {
        int i = tid + k * 256;
        int c = i >> 5, q = i & 31;
        uint2 u = __ldg(&m2[((b * Cc + c) * Tt + t0) * (Vv / 4) + (v0 >> 2) + q]);
        *reinterpret_cast<uint2*>(&scat[(32 + c) * 136 + q * 4]) = u;
    }
    // B-fragment table: 1024 u32 = one uint4 per thread
    reinterpret_cast<uint4*>(s_bf)[tid] =
        __ldg(&reinterpret_cast<const uint4*>(g_bfrag)[tid]);
    if (tid < 32) sfb[tid] = fb[tid];
    if (tid < 128) s_cv[tid] = g_cv[(size_t)(b * Tt + t0) * Vv + v0 + tid];
    __syncthreads();

    float acc[4][4];
#pragma unroll
    for (int nt = 0; nt < 4; ++nt)
#pragma unroll
        for (int i = 0; i < 4; ++i) acc[nt][i] = 0.f;

    // A fragments via ldmatrix.x4.trans; 16 mma per warp (validated R12)
    unsigned sbase = (unsigned)__cvta_generic_to_shared(scat);
    int p0w  = warp * 16;
    int tile = lane >> 3, r = lane & 7;
    int kofs = (tile >> 1) * 8 + r;
    int pofs = p0w + (tile & 1) * 8;
#pragma unroll
    for (int kc = 0; kc < 4; ++kc) {
        unsigned addr = sbase + (unsigned)(((kc * 16 + kofs) * 136 + pofs) * 2);
        unsigned a0, a1, a2, a3;
        asm volatile(
            "ldmatrix.sync.aligned.m8n8.x4.trans.shared.b16 {%0,%1,%2,%3}, [%4];"
            : "=r"(a0), "=r"(a1), "=r"(a2), "=r"(a3) : "r"(addr));
#pragma unroll
        for (int nt = 0; nt < 4; ++nt) {
            uint2 bw = *reinterpret_cast<const uint2*>(
                &s_bf[(nt * 4 + kc) * 64 + (lane << 1)]);
            asm volatile(
                "mma.sync.aligned.m16n8k16.row.col.f32.bf16.bf16.f32 "
                "{%0,%1,%2,%3}, {%4,%5,%6,%7}, {%8,%9}, {%0,%1,%2,%3};"
                : "+f"(acc[nt][0]), "+f"(acc[nt][1]),
                  "+f"(acc[nt][2]), "+f"(acc[nt][3])
                : "r"(a0), "r"(a1), "r"(a2), "r"(a3),
                  "r"(bw.x), "r"(bw.y));
        }
    }

    // epilogue (validated R12)
    float imp = __ldg(g_imp + b * Tt + t0);
    int eo = (lane & 3) * 2;
    int ep = p0w + (lane >> 2);
    float m_lo = 1.f + s_cv[ep];
    float m_hi = 1.f + s_cv[ep + 8];
#pragma unroll
    for (int nt = 0; nt < 4; ++nt) {
        int o0 = nt * 8 + eo;
        float f0 = sfb[o0], f1 = sfb[o0 + 1];
        s_out[o0 * 132 + ep]            = (acc[nt][0] + f0) * m_lo + imp;
        s_out[(o0 + 1) * 132 + ep]      = (acc[nt][1] + f1) * m_lo + imp;
        s_out[o0 * 132 + ep + 8]        = (acc[nt][2] + f0) * m_hi + imp;
        s_out[(o0 + 1) * 132 + ep + 8]  = (acc[nt][3] + f1) * m_hi + imp;
    }
    __syncthreads();

#pragma unroll
    for (int k = 0; k < 4; ++k) {
        int i = tid + k * 256;            // 0..1023
        int o = i >> 5, pq = i & 31;
        float4 v = *reinterpret_cast<const float4*>(&s_out[o * 132 + pq * 4]);
        *reinterpret_cast<float4*>(
            &out[((size_t)(b * Cc + o) * Tt + t0) * Vv + v0 + pq * 4]) = v;
    }
}

// ---------------------------------------------------------------------------
extern "C" void kernel_launch(void* const* d_in, const int* in_sizes, int n_in,
                              void* d_out, int out_size) {
    const float* flow   = (const float*)d_in[0];
    const float* events = (const float*)d_in[1];
    const float* x      = (const float*)d_in[2];
    const float* ef     = (const float*)d_in[3];
    const float* w1     = (const float*)d_in[4];
    const float* b1     = (const float*)d_in[5];
    const float* w2     = (const float*)d_in[6];
    const float* b2     = (const float*)d_in[7];
    const float* fw     = (const float*)d_in[8];
    const float* fb     = (const float*)d_in[9];
    float* out = (float*)d_out;

    const int smem_kM = 64 * 128 * sizeof(float2);   // 64 KB
    cudaFuncSetAttribute(kM, cudaFuncAttributeMaxDynamicSharedMemorySize,
                         smem_kM);

    kM<<<1090, 128, smem_kM>>>(x, flow, events, ef, w1, b1, w2, b2, fw);
    k2t<<<dim3(Vv / 128, Tt, Bc), 256>>>(x, fb, out);
}

// round 14
// speedup vs baseline: 2.7830x; 1.0868x over previous
#include <cuda_runtime.h>
#include <cuda_bf16.h>
#include <math.h>

#define Bc 4
#define Tt 288
#define Vv 512
#define Cc 32

// scratch (static __device__ arrays: allowed, no runtime allocation)
__device__ unsigned g_comb[Bc * Cc * Tt * 256];   // bf16x2, 37.7 MB
__device__ unsigned g_xbf[Bc * Cc * Tt * 256];    // bf16x2 copy of x, 37.7 MB
__device__ float g_cv[Bc * Tt * Vv];              // 2.36 MB
__device__ float g_imp[Bc * Tt];
__device__ unsigned g_bfrag[16 * 64];             // 4 KB B-fragments

__device__ __forceinline__ unsigned packbf(float a, float b) {
    __nv_bfloat162 h = __floats2bfloat162_rn(a, b);   // .x = a (low half)
    return *reinterpret_cast<unsigned*>(&h);
}
__device__ __forceinline__ float2 unpackbf(unsigned u) {
    return __bfloat1622float2(*reinterpret_cast<__nv_bfloat162*>(&u));
}

// ---------------------------------------------------------------------------
// kM: merged front kernel.
//   blocks [0,512): expert filter, 2-way t-split (R8-validated 216-step/144-
//                   output scheme, 49-step zero-ring warm-up), bf16 ring.
//                   Also writes bf16 x copy (g_xbf) once per element.
//   blocks [512,576): rolling CV   block 576: impact   block 577: B-fragments
// ---------------------------------------------------------------------------
__global__ void __launch_bounds__(128) kM(
    const float* __restrict__ xf, const float* __restrict__ flow,
    const float* __restrict__ events, const float* __restrict__ ef,
    const float* __restrict__ w1, const float* __restrict__ b1,
    const float* __restrict__ w2, const float* __restrict__ b2,
    const float* __restrict__ fw)
{
    extern __shared__ __align__(16) float dsm[];
    int tid = threadIdx.x;
    int bx = blockIdx.x;

    if (bx >= 512) {
        if (bx < 576) {
            // ---- rolling CV role (validated) ----
            float* sf = dsm;                       // 288*32 floats = 36 KB
            int idx = bx - 512;
            int b  = idx >> 4;
            int v0 = (idx & 15) * 32;
            for (int i = tid; i < Tt * 32; i += 128) {
                int t = i >> 5, v = i & 31;
                sf[i] = flow[(size_t)(b * Tt + t) * Vv + v0 + v];
            }
            __syncthreads();
            int v = tid & 31;
            int ch = tid >> 5;
            int ts = ch * 72;
            float s = 0.f, s2 = 0.f;
            int j0 = ts - 60; if (j0 < 0) j0 = 0;
            for (int j = j0; j < ts; ++j) {
                float f = sf[j * 32 + v];
                s += f; s2 += f * f;
            }
            float* cp = g_cv + (size_t)b * Tt * Vv + v0 + v;
#pragma unroll 4
            for (int t = ts; t < ts + 72; ++t) {
                float f = sf[t * 32 + v];
                s += f; s2 += f * f;
                if (t >= 60) {
                    float fo = sf[(t - 60) * 32 + v];
                    s -= fo; s2 -= fo * fo;
                }
                float c = 0.f;
                if (t >= 59) {
                    float mean = s * (1.f / 60.f);
                    float var = (s2 - 60.f * mean * mean) * (1.f / 59.f);
                    var = fmaxf(var, 0.f);
                    c = sqrtf(var) / (mean + 1e-6f);
                }
                cp[(size_t)t * Vv] = c;
            }
        } else if (bx == 576) {
            // ---- impact scan role (validated) ----
            float* sev  = dsm;
            float* part = dsm + Bc * Tt * 3;
            for (int i = tid; i < Bc * Tt * 3; i += 128) sev[i] = events[i];
            __syncthreads();
            if (tid < 12) {
                int b = tid / 3, e = tid % 3;
                const float decay[3] = {300.f, 600.f, 180.f};
                const float alpha[3] = {0.3f, 0.5f, 0.2f};
                float r = expf(-1.f / decay[e]);
                float a = alpha[e];
                float s = 0.f;
                for (int t = Tt - 1; t >= 0; --t) {
                    s = sev[(b * Tt + t) * 3 + e] + r * s;
                    part[tid * Tt + t] = a * s;
                }
            }
            __syncthreads();
            for (int i = tid; i < Bc * Tt; i += 128) {
                int b = i / Tt, t = i - b * Tt;
                g_imp[i] = part[(b * 3 + 0) * Tt + t] +
                           part[(b * 3 + 1) * Tt + t] +
                           part[(b * 3 + 2) * Tt + t];
            }
        } else {
            // ---- B-fragment table role (validated R13) ----
            if (tid < 32) {
                int bn = tid >> 2, bk = (tid & 3) * 2;
#pragma unroll
                for (int nt = 0; nt < 4; ++nt)
#pragma unroll
                    for (int kc = 0; kc < 4; ++kc) {
                        int n = nt * 8 + bn;
                        int k0 = kc * 16 + bk;
                        float w00 = fw[n * 64 + k0]     + (k0     == n ? 1.f : 0.f);
                        float w01 = fw[n * 64 + k0 + 1] + (k0 + 1 == n ? 1.f : 0.f);
                        float w80 = fw[n * 64 + k0 + 8] + (k0 + 8 == n ? 1.f : 0.f);
                        float w81 = fw[n * 64 + k0 + 9] + (k0 + 9 == n ? 1.f : 0.f);
                        g_bfrag[(nt * 4 + kc) * 64 + tid * 2 + 0] = packbf(w00, w01);
                        g_bfrag[(nt * 4 + kc) * 64 + tid * 2 + 1] = packbf(w80, w81);
                    }
            }
        }
        return;
    }

    // ---- expert filter role: 2-way t-split, bf16 ring ----
    unsigned* rs = (unsigned*)dsm;                 // [64][128] bf16x2 = 32 KB
    __shared__ float sh[32];
    __shared__ float slg[5];
    __shared__ float scoef[5];

    int cb   = bx & 255;                           // column block 0..255
    int half = bx >> 8;                            // 0 or 1
    int ts   = half * 144;                         // outputs [ts, ts+144)
    int idx = cb * 128 + tid;                      // 0..32767
    int vp = idx & 255;
    int bc = idx >> 8;                             // constant per block
    int b  = bc >> 5;

    // inline MLP -> coefs (validated R11)
    if (tid < 32) {
        float acc = b1[tid];
#pragma unroll
        for (int i = 0; i < 8; ++i) acc += ef[b * 8 + i] * w1[i * 32 + tid];
        sh[tid] = fmaxf(acc, 0.f);
    }
    __syncthreads();
    if (tid < 5) {
        float acc = b2[tid];
#pragma unroll
        for (int j = 0; j < 32; ++j) acc += sh[j] * w2[j * 5 + tid];
        slg[tid] = 1.f / (1.f + expf(-acc));
    }
    __syncthreads();
    if (tid == 0) {
        float m = fmaxf(fmaxf(fmaxf(slg[0], slg[1]), fmaxf(slg[2], slg[3])),
                        slg[4]);
        float ex[5], ssum = 0.f;
#pragma unroll
        for (int k = 0; k < 5; ++k) { ex[k] = expf(slg[k] - m); ssum += ex[k]; }
        const float ks[5] = {3.f, 6.f, 12.f, 24.f, 48.f};
#pragma unroll
        for (int k = 0; k < 5; ++k) scoef[k] = ex[k] / (ssum * ks[k]);
    }

    const float2* xp = (const float2*)xf + (size_t)bc * Tt * 256 + vp;
    unsigned* cp = g_comb + (size_t)bc * Tt * 256 + vp;
    unsigned* xq = g_xbf  + (size_t)bc * Tt * 256 + vp;

#pragma unroll
    for (int s = 0; s < 64; ++s) rs[s * 128 + tid] = 0u;
    __syncthreads();

    float c0 = scoef[0], c1 = scoef[1], c2 = scoef[2], c3 = scoef[3],
          c4 = scoef[4];

    float2 S0 = make_float2(0.f, 0.f), S1 = S0, S2 = S0, S3 = S0, S4 = S0;

    float2 f[8];
#pragma unroll
    for (int j = 0; j < 8; ++j) {
        int tn = ts - 49 + j;
        f[j] = ((unsigned)tn < (unsigned)Tt)
                 ? __ldg(xp + (size_t)tn * 256) : make_float2(0.f, 0.f);
    }

    int tin = ts - 49;
    int tout0 = ts + 23;
    for (int g = 0; g < 27; ++g) {                 // 27*8 = 216 steps
#pragma unroll
        for (int j = 0; j < 8; ++j) {
            unsigned uin = packbf(f[j].x, f[j].y);   // rounded once
            float2 zin = unpackbf(uin);              // used for S4 add
            float2 a3  = unpackbf(rs[((tin - 22) & 63) * 128 + tid]);
            float2 a6  = unpackbf(rs[((tin - 21) & 63) * 128 + tid]);
            float2 a12 = unpackbf(rs[((tin - 18) & 63) * 128 + tid]);
            float2 a24 = unpackbf(rs[((tin - 12) & 63) * 128 + tid]);
            float2 d3  = unpackbf(rs[((tin - 25) & 63) * 128 + tid]);
            float2 d6  = unpackbf(rs[((tin - 27) & 63) * 128 + tid]);
            float2 d12 = unpackbf(rs[((tin - 30) & 63) * 128 + tid]);
            float2 d24 = unpackbf(rs[((tin - 36) & 63) * 128 + tid]);
            float2 d48 = unpackbf(rs[((tin - 48) & 63) * 128 + tid]);

            S0.x += a3.x  - d3.x;   S0.y += a3.y  - d3.y;
            S1.x += a6.x  - d6.x;   S1.y += a6.y  - d6.y;
            S2.x += a12.x - d12.x;  S2.y += a12.y - d12.y;
            S3.x += a24.x - d24.x;  S3.y += a24.y - d24.y;
            S4.x += zin.x - d48.x;  S4.y += zin.y - d48.y;

            rs[(tin & 63) * 128 + tid] = uin;

            if ((unsigned)(tin - ts) < 144u)       // x bf16 copy, once/element
                xq[(size_t)tin * 256] = uin;

            if (tin >= tout0) {
                float ox = c0 * S0.x + c1 * S1.x + c2 * S2.x + c3 * S3.x +
                           c4 * S4.x;
                float oy = c0 * S0.y + c1 * S1.y + c2 * S2.y + c3 * S3.y +
                           c4 * S4.y;
                cp[(size_t)(tin - 23) * 256] = packbf(ox, oy);
            }
            int tn = tin + 8;
            f[j] = ((unsigned)tn < (unsigned)Tt)
                     ? __ldg(xp + (size_t)tn * 256) : make_float2(0.f, 0.f);
            ++tin;
        }
    }
}

// ---------------------------------------------------------------------------
// k2t v3: tensor-core channel mix (validated R13 MMA structure). Both tile
// fills are now raw uint4 copies (x comes pre-converted from g_xbf).
// ---------------------------------------------------------------------------
__global__ void __launch_bounds__(256) k2t(const float* __restrict__ fb,
                                           float* __restrict__ out) {
    __shared__ __align__(16) __nv_bfloat16 scat[64 * 136];   // 17408 B
    __shared__ __align__(16) float s_out[32 * 132];          // 16896 B
    __shared__ __align__(16) unsigned s_bf[16 * 64];         // 4096 B
    __shared__ float s_cv[128];
    __shared__ float sfb[32];

    int tid  = threadIdx.x;
    int lane = tid & 31;
    int warp = tid >> 5;
    int v0 = blockIdx.x * 128;
    int t0 = blockIdx.y;
    int b  = blockIdx.z;

    // fill x rows (raw bf16 copy)
    const uint4* xb4 = reinterpret_cast<const uint4*>(g_xbf);
#pragma unroll
    for (int k = 0; k < 2; ++k) {
        int i = tid + k * 256;            // 0..511
        int c = i >> 4, q = i & 15;
        uint4 u = __ldg(&xb4[((b * Cc + c) * Tt + t0) * 64 + (v0 >> 3) + q]);
        *reinterpret_cast<uint4*>(&scat[c * 136 + q * 8]) = u;
    }
    // fill comb rows (raw bf16 copy)
    const uint4* m4 = reinterpret_cast<const uint4*>(g_comb);
#pragma unroll
    for (int k = 0; k < 2; ++k) {
        int i = tid + k * 256;
        int c = i >> 4, q = i & 15;
        uint4 u = __ldg(&m4[((b * Cc + c) * Tt + t0) * 64 + (v0 >> 3) + q]);
        *reinterpret_cast<uint4*>(&scat[(32 + c) * 136 + q * 8]) = u;
    }
    // B-fragment table: 1024 u32 = one uint4 per thread
    reinterpret_cast<uint4*>(s_bf)[tid] =
        __ldg(&reinterpret_cast<const uint4*>(g_bfrag)[tid]);
    if (tid < 32) sfb[tid] = fb[tid];
    if (tid < 128) s_cv[tid] = g_cv[(size_t)(b * Tt + t0) * Vv + v0 + tid];
    __syncthreads();

    float acc[4][4];
#pragma unroll
    for (int nt = 0; nt < 4; ++nt)
#pragma unroll
        for (int i = 0; i < 4; ++i) acc[nt][i] = 0.f;

    // A fragments via ldmatrix.x4.trans; 16 mma per warp (validated R12)
    unsigned sbase = (unsigned)__cvta_generic_to_shared(scat);
    int p0w  = warp * 16;
    int tile = lane >> 3, r = lane & 7;
    int kofs = (tile >> 1) * 8 + r;
    int pofs = p0w + (tile & 1) * 8;
#pragma unroll
    for (int kc = 0; kc < 4; ++kc) {
        unsigned addr = sbase + (unsigned)(((kc * 16 + kofs) * 136 + pofs) * 2);
        unsigned a0, a1, a2, a3;
        asm volatile(
            "ldmatrix.sync.aligned.m8n8.x4.trans.shared.b16 {%0,%1,%2,%3}, [%4];"
            : "=r"(a0), "=r"(a1), "=r"(a2), "=r"(a3) : "r"(addr));
#pragma unroll
        for (int nt = 0; nt < 4; ++nt) {
            uint2 bw = *reinterpret_cast<const uint2*>(
                &s_bf[(nt * 4 + kc) * 64 + (lane << 1)]);
            asm volatile(
                "mma.sync.aligned.m16n8k16.row.col.f32.bf16.bf16.f32 "
                "{%0,%1,%2,%3}, {%4,%5,%6,%7}, {%8,%9}, {%0,%1,%2,%3};"
                : "+f"(acc[nt][0]), "+f"(acc[nt][1]),
                  "+f"(acc[nt][2]), "+f"(acc[nt][3])
                : "r"(a0), "r"(a1), "r"(a2), "r"(a3),
                  "r"(bw.x), "r"(bw.y));
        }
    }

    // epilogue (validated R12)
    float imp = __ldg(g_imp + b * Tt + t0);
    int eo = (lane & 3) * 2;
    int ep = p0w + (lane >> 2);
    float m_lo = 1.f + s_cv[ep];
    float m_hi = 1.f + s_cv[ep + 8];
#pragma unroll
    for (int nt = 0; nt < 4; ++nt) {
        int o0 = nt * 8 + eo;
        float f0 = sfb[o0], f1 = sfb[o0 + 1];
        s_out[o0 * 132 + ep]            = (acc[nt][0] + f0) * m_lo + imp;
        s_out[(o0 + 1) * 132 + ep]      = (acc[nt][1] + f1) * m_lo + imp;
        s_out[o0 * 132 + ep + 8]        = (acc[nt][2] + f0) * m_hi + imp;
        s_out[(o0 + 1) * 132 + ep + 8]  = (acc[nt][3] + f1) * m_hi + imp;
    }
    __syncthreads();

#pragma unroll
    for (int k = 0; k < 4; ++k) {
        int i = tid + k * 256;            // 0..1023
        int o = i >> 5, pq = i & 31;
        float4 v = *reinterpret_cast<const float4*>(&s_out[o * 132 + pq * 4]);
        *reinterpret_cast<float4*>(
            &out[((size_t)(b * Cc + o) * Tt + t0) * Vv + v0 + pq * 4]) = v;
    }
}

// ---------------------------------------------------------------------------
extern "C" void kernel_launch(void* const* d_in, const int* in_sizes, int n_in,
                              void* d_out, int out_size) {
    const float* flow   = (const float*)d_in[0];
    const float* events = (const float*)d_in[1];
    const float* x      = (const float*)d_in[2];
    const float* ef     = (const float*)d_in[3];
    const float* w1     = (const float*)d_in[4];
    const float* b1     = (const float*)d_in[5];
    const float* w2     = (const float*)d_in[6];
    const float* b2     = (const float*)d_in[7];
    const float* fw     = (const float*)d_in[8];
    const float* fb     = (const float*)d_in[9];
    float* out = (float*)d_out;

    const int smem_kM = Tt * 32 * sizeof(float);   // 36864 B (cv role max)
    cudaFuncSetAttribute(kM, cudaFuncAttributeMaxDynamicSharedMemorySize,
                         smem_kM);

    kM<<<578, 128, smem_kM>>>(x, flow, events, ef, w1, b1, w2, b2, fw);
    k2t<<<dim3(Vv / 128, Tt, Bc), 256>>>(fb, out);
}

// round 17
// speedup vs baseline: 2.8329x; 1.0179x over previous
#include <cuda_runtime.h>
#include <cuda_bf16.h>
#include <math.h>

#define Bc 4
#define Tt 288
#define Vv 512
#define Cc 32

// scratch (static __device__ arrays: allowed, no runtime allocation)
__device__ unsigned g_comb[Bc * Cc * Tt * 256];   // bf16x2 filter(x), 37.7 MB
__device__ unsigned g_xbf[Bc * Cc * Tt * 256];    // bf16x2 copy of x, 37.7 MB
__device__ float g_cv[Bc * Tt * Vv];              // 2.36 MB
__device__ float g_imp[Bc * Tt];
__device__ unsigned g_bfrag[16 * 64];             // W' fragments (k2t), 4 KB
__device__ unsigned g_bfragH[36 * 1536];          // H fragments (kG), 221 KB

__device__ __forceinline__ unsigned packbf(float a, float b) {
    __nv_bfloat162 h = __floats2bfloat162_rn(a, b);   // .x = a (low half)
    return *reinterpret_cast<unsigned*>(&h);
}

// ---------------------------------------------------------------------------
// kF2: front kernel.
//   blocks [0,64): rolling CV (validated R14)      block 64: impact scan
//   block 65: W' B-fragment table (validated R13)
//   blocks [66,102): H B-fragment tables, one per (b, t-tile i).
//     H_b[tout][tin] = h_b[tin-tout], h[d] = sum_k c_k * 1[lo_k<=d<=hi_k],
//     c_k = softmax(sigmoid(logits))_k / k  (inline MLP, validated R11).
//     Table layout mirrors R13: entry (nt,kc,lane,j):
//       n = nt*8 + (lane>>2), k0 = kc*16 + (lane&3)*2 + j*8
//       val = pack(B[k0][n], B[k0+1][n]),  B[k][n] = H[32i+n][32i-32+k]
// ---------------------------------------------------------------------------
__global__ void __launch_bounds__(128) kF2(
    const float* __restrict__ flow, const float* __restrict__ events,
    const float* __restrict__ ef,
    const float* __restrict__ w1, const float* __restrict__ b1,
    const float* __restrict__ w2, const float* __restrict__ b2,
    const float* __restrict__ fw)
{
    extern __shared__ __align__(16) float dsm[];
    __shared__ float sh[32];
    __shared__ float slg[5];
    __shared__ float scoef[5];
    __shared__ float shh[48];
    int tid = threadIdx.x;
    int bx = blockIdx.x;

    if (bx < 64) {
        // ---- rolling CV role (validated) ----
        float* sf = dsm;
        int b  = bx >> 4;
        int v0 = (bx & 15) * 32;
        for (int i = tid; i < Tt * 32; i += 128) {
            int t = i >> 5, v = i & 31;
            sf[i] = flow[(size_t)(b * Tt + t) * Vv + v0 + v];
        }
        __syncthreads();
        int v = tid & 31;
        int ch = tid >> 5;
        int ts = ch * 72;
        float s = 0.f, s2 = 0.f;
        int j0 = ts - 60; if (j0 < 0) j0 = 0;
        for (int j = j0; j < ts; ++j) {
            float f = sf[j * 32 + v];
            s += f; s2 += f * f;
        }
        float* cp = g_cv + (size_t)b * Tt * Vv + v0 + v;
#pragma unroll 4
        for (int t = ts; t < ts + 72; ++t) {
            float f = sf[t * 32 + v];
            s += f; s2 += f * f;
            if (t >= 60) {
                float fo = sf[(t - 60) * 32 + v];
                s -= fo; s2 -= fo * fo;
            }
            float c = 0.f;
            if (t >= 59) {
                float mean = s * (1.f / 60.f);
                float var = (s2 - 60.f * mean * mean) * (1.f / 59.f);
                var = fmaxf(var, 0.f);
                c = sqrtf(var) / (mean + 1e-6f);
            }
            cp[(size_t)t * Vv] = c;
        }
    } else if (bx == 64) {
        // ---- impact scan role (validated) ----
        float* sev  = dsm;
        float* part = dsm + Bc * Tt * 3;
        for (int i = tid; i < Bc * Tt * 3; i += 128) sev[i] = events[i];
        __syncthreads();
        if (tid < 12) {
            int b = tid / 3, e = tid % 3;
            const float decay[3] = {300.f, 600.f, 180.f};
            const float alpha[3] = {0.3f, 0.5f, 0.2f};
            float r = expf(-1.f / decay[e]);
            float a = alpha[e];
            float s = 0.f;
            for (int t = Tt - 1; t >= 0; --t) {
                s = sev[(b * Tt + t) * 3 + e] + r * s;
                part[tid * Tt + t] = a * s;
            }
        }
        __syncthreads();
        for (int i = tid; i < Bc * Tt; i += 128) {
            int b = i / Tt, t = i - b * Tt;
            g_imp[i] = part[(b * 3 + 0) * Tt + t] +
                       part[(b * 3 + 1) * Tt + t] +
                       part[(b * 3 + 2) * Tt + t];
        }
    } else if (bx == 65) {
        // ---- W' B-fragment table (validated R13) ----
        if (tid < 32) {
            int bn = tid >> 2, bk = (tid & 3) * 2;
#pragma unroll
            for (int nt = 0; nt < 4; ++nt)
#pragma unroll
                for (int kc = 0; kc < 4; ++kc) {
                    int n = nt * 8 + bn;
                    int k0 = kc * 16 + bk;
                    float w00 = fw[n * 64 + k0]     + (k0     == n ? 1.f : 0.f);
                    float w01 = fw[n * 64 + k0 + 1] + (k0 + 1 == n ? 1.f : 0.f);
                    float w80 = fw[n * 64 + k0 + 8] + (k0 + 8 == n ? 1.f : 0.f);
                    float w81 = fw[n * 64 + k0 + 9] + (k0 + 9 == n ? 1.f : 0.f);
                    g_bfrag[(nt * 4 + kc) * 64 + tid * 2 + 0] = packbf(w00, w01);
                    g_bfrag[(nt * 4 + kc) * 64 + tid * 2 + 1] = packbf(w80, w81);
                }
        }
    } else {
        // ---- H B-fragment tables ----
        int idx = bx - 66;                 // 0..35
        int b  = idx / 9;
        int ti = idx % 9;

        // inline MLP -> coefs (validated R11)
        if (tid < 32) {
            float acc = b1[tid];
#pragma unroll
            for (int i = 0; i < 8; ++i) acc += ef[b * 8 + i] * w1[i * 32 + tid];
            sh[tid] = fmaxf(acc, 0.f);
        }
        __syncthreads();
        if (tid < 5) {
            float acc = b2[tid];
#pragma unroll
            for (int j = 0; j < 32; ++j) acc += sh[j] * w2[j * 5 + tid];
            slg[tid] = 1.f / (1.f + expf(-acc));
        }
        __syncthreads();
        if (tid == 0) {
            float m = fmaxf(fmaxf(fmaxf(slg[0], slg[1]), fmaxf(slg[2], slg[3])),
                            slg[4]);
            float ex[5], ssum = 0.f;
#pragma unroll
            for (int k = 0; k < 5; ++k) { ex[k] = expf(slg[k] - m); ssum += ex[k]; }
            const float ks[5] = {3.f, 6.f, 12.f, 24.f, 48.f};
#pragma unroll
            for (int k = 0; k < 5; ++k) scoef[k] = ex[k] / (ssum * ks[k]);
        }
        __syncthreads();
        // h[d], d = -24..23 (stored at shh[d+24])
        if (tid < 48) {
            int d = tid - 24;
            const int lo[5] = {-1, -3, -6, -12, -24};
            const int hi[5] = {1, 2, 5, 11, 23};
            float h = 0.f;
#pragma unroll
            for (int k = 0; k < 5; ++k)
                if (d >= lo[k] && d <= hi[k]) h += scoef[k];
            shh[tid] = h;
        }
        __syncthreads();
        // build table: 1536 entries
        unsigned* tb = g_bfragH + idx * 1536;
        for (int e = tid; e < 1536; e += 128) {
            int l = (e & 63) >> 1, j = e & 1;
            int g = e >> 6;
            int nt = g / 6, kc = g % 6;
            int n  = nt * 8 + (l >> 2);
            int k0 = kc * 16 + (l & 3) * 2 + j * 8;
            float v0f = 0.f, v1f = 0.f;
#pragma unroll
            for (int u = 0; u < 2; ++u) {
                int k = k0 + u;
                int tin = 32 * ti - 32 + k;
                int d = k - 32 - n;               // tin - tout
                float h = 0.f;
                if (tin >= 0 && tin < Tt && d >= -24 && d <= 23)
                    h = shh[d + 24];
                if (u == 0) v0f = h; else v1f = h;
            }
            tb[e] = packbf(v0f, v1f);
        }
    }
}

// ---------------------------------------------------------------------------
// kG: banded filter GEMM. Z[tout 32][v 128] = sum_k H[tout][tin] * x[tin][v]
// per (b,c), K = 96 (3 input t-tiles). Mirrors the validated k2t MMA scheme:
// A = X^T via ldmatrix.x4.trans from Xs[tin][136-pad v] (bf16, converted from
// fp32 x during fill), B from precomputed g_bfragH table. Also writes the
// bf16 x copy (g_xbf) for its own 32-t tile.
// ---------------------------------------------------------------------------
__global__ void __launch_bounds__(256) kG(const float* __restrict__ x) {
    __shared__ __align__(16) __nv_bfloat16 Xs[96 * 136];     // 26112 B
    __shared__ __align__(16) __nv_bfloat16 s_z[32 * 136];    // 8704 B
    __shared__ __align__(16) unsigned s_bf[1536];            // 6144 B

    int tid  = threadIdx.x;
    int lane = tid & 31;
    int warp = tid >> 5;
    int v0 = blockIdx.x * 128;
    int ti = blockIdx.y;               // t-tile 0..8
    int bc = blockIdx.z;               // b*32 + c
    int b  = bc >> 5;

    // fill Xs: 96 rows (tin = 32*ti-32+k) x 128 v, fp32 -> bf16
    const float4* x4 = reinterpret_cast<const float4*>(x);
#pragma unroll
    for (int m = 0; m < 12; ++m) {
        int i = tid + m * 256;         // 0..3071
        int k = i >> 5, q = i & 31;    // row k, float4-col q (v = q*4)
        int tin = 32 * ti - 32 + k;
        unsigned lo = 0u, hi = 0u;
        if ((unsigned)tin < (unsigned)Tt) {
            float4 v = x4[((size_t)bc * Tt + tin) * (Vv / 4) + (v0 >> 2) + q];
            lo = packbf(v.x, v.y);
            hi = packbf(v.z, v.w);
        }
        *reinterpret_cast<uint2*>(
            reinterpret_cast<char*>(Xs) + k * 272 + q * 8) = make_uint2(lo, hi);
    }
    // B-fragment table: 1536 u32 = 384 uint4 (256 threads -> strided loop!)
    for (int i = tid; i < 384; i += 256)
        reinterpret_cast<uint4*>(s_bf)[i] =
            __ldg(&reinterpret_cast<const uint4*>(
                g_bfragH + (size_t)(b * 9 + ti) * 1536)[i]);
    __syncthreads();

    // write g_xbf for own rows (k = 32..63 -> t = 32*ti + o)
    {
        uint4* xq = reinterpret_cast<uint4*>(g_xbf);
#pragma unroll
        for (int m = 0; m < 2; ++m) {
            int i = tid + m * 256;     // 0..511
            int o = i >> 4, q = i & 15;
            uint4 u = *reinterpret_cast<const uint4*>(
                reinterpret_cast<const char*>(Xs) + (32 + o) * 272 + q * 16);
            xq[((size_t)bc * Tt + 32 * ti + o) * 64 + (v0 >> 3) + q] = u;
        }
    }

    float acc[4][4];
#pragma unroll
    for (int nt = 0; nt < 4; ++nt)
#pragma unroll
        for (int i = 0; i < 4; ++i) acc[nt][i] = 0.f;

    // A via ldmatrix.x4.trans (validated scheme), 6 kc x 4 nt mma
    unsigned sbase = (unsigned)__cvta_generic_to_shared(Xs);
    int p0w  = warp * 16;
    int tile = lane >> 3, r = lane & 7;
    int kofs = (tile >> 1) * 8 + r;
    int pofs = p0w + (tile & 1) * 8;
#pragma unroll
    for (int kc = 0; kc < 6; ++kc) {
        unsigned addr = sbase + (unsigned)(((kc * 16 + kofs) * 136 + pofs) * 2);
        unsigned a0, a1, a2, a3;
        asm volatile(
            "ldmatrix.sync.aligned.m8n8.x4.trans.shared.b16 {%0,%1,%2,%3}, [%4];"
            : "=r"(a0), "=r"(a1), "=r"(a2), "=r"(a3) : "r"(addr));
#pragma unroll
        for (int nt = 0; nt < 4; ++nt) {
            uint2 bw = *reinterpret_cast<const uint2*>(
                &s_bf[(nt * 6 + kc) * 64 + (lane << 1)]);
            asm volatile(
                "mma.sync.aligned.m16n8k16.row.col.f32.bf16.bf16.f32 "
                "{%0,%1,%2,%3}, {%4,%5,%6,%7}, {%8,%9}, {%0,%1,%2,%3};"
                : "+f"(acc[nt][0]), "+f"(acc[nt][1]),
                  "+f"(acc[nt][2]), "+f"(acc[nt][3])
                : "r"(a0), "r"(a1), "r"(a2), "r"(a3),
                  "r"(bw.x), "r"(bw.y));
        }
    }

    // pack to s_z[tout][v] (bf16), then coalesced copy to g_comb
    int eo = (lane & 3) * 2;
    int ep = p0w + (lane >> 2);
#pragma unroll
    for (int nt = 0; nt < 4; ++nt) {
        int o0 = nt * 8 + eo;
        s_z[o0 * 136 + ep]           = __float2bfloat16(acc[nt][0]);
        s_z[(o0 + 1) * 136 + ep]     = __float2bfloat16(acc[nt][1]);
        s_z[o0 * 136 + ep + 8]       = __float2bfloat16(acc[nt][2]);
        s_z[(o0 + 1) * 136 + ep + 8] = __float2bfloat16(acc[nt][3]);
    }
    __syncthreads();

    {
        uint4* cq = reinterpret_cast<uint4*>(g_comb);
#pragma unroll
        for (int m = 0; m < 2; ++m) {
            int i = tid + m * 256;     // 0..511
            int o = i >> 4, q = i & 15;
            uint4 u = *reinterpret_cast<const uint4*>(
                reinterpret_cast<const char*>(s_z) + o * 272 + q * 16);
            cq[((size_t)bc * Tt + 32 * ti + o) * 64 + (v0 >> 3) + q] = u;
        }
    }
}

// ---------------------------------------------------------------------------
// k2t (verbatim R14, validated): tensor-core channel mix + epilogue.
// ---------------------------------------------------------------------------
__global__ void __launch_bounds__(256) k2t(const float* __restrict__ fb,
                                           float* __restrict__ out) {
    __shared__ __align__(16) __nv_bfloat16 scat[64 * 136];
    __shared__ __align__(16) float s_out[32 * 132];
    __shared__ __align__(16) unsigned s_bf[16 * 64];
    __shared__ float s_cv[128];
    __shared__ float sfb[32];

    int tid  = threadIdx.x;
    int lane = tid & 31;
    int warp = tid >> 5;
    int v0 = blockIdx.x * 128;
    int t0 = blockIdx.y;
    int b  = blockIdx.z;

    const uint4* xb4 = reinterpret_cast<const uint4*>(g_xbf);
#pragma unroll
    for (int k = 0; k < 2; ++k) {
        int i = tid + k * 256;
        int c = i >> 4, q = i & 15;
        uint4 u = __ldg(&xb4[((b * Cc + c) * Tt + t0) * 64 + (v0 >> 3) + q]);
        *reinterpret_cast<uint4*>(&scat[c * 136 + q * 8]) = u;
    }
    const uint4* m4 = reinterpret_cast<const uint4*>(g_comb);
#pragma unroll
    for (int k = 0; k < 2; ++k) {
        int i = tid + k * 256;
        int c = i >> 4, q = i & 15;
        uint4 u = __ldg(&m4[((b * Cc + c) * Tt + t0) * 64 + (v0 >> 3) + q]);
        *reinterpret_cast<uint4*>(&scat[(32 + c) * 136 + q * 8]) = u;
    }
    reinterpret_cast<uint4*>(s_bf)[tid] =
        __ldg(&reinterpret_cast<const uint4*>(g_bfrag)[tid]);
    if (tid < 32) sfb[tid] = fb[tid];
    if (tid < 128) s_cv[tid] = g_cv[(size_t)(b * Tt + t0) * Vv + v0 + tid];
    __syncthreads();

    float acc[4][4];
#pragma unroll
    for (int nt = 0; nt < 4; ++nt)
#pragma unroll
        for (int i = 0; i < 4; ++i) acc[nt][i] = 0.f;

    unsigned sbase = (unsigned)__cvta_generic_to_shared(scat);
    int p0w  = warp * 16;
    int tile = lane >> 3, r = lane & 7;
    int kofs = (tile >> 1) * 8 + r;
    int pofs = p0w + (tile & 1) * 8;
#pragma unroll
    for (int kc = 0; kc < 4; ++kc) {
        unsigned addr = sbase + (unsigned)(((kc * 16 + kofs) * 136 + pofs) * 2);
        unsigned a0, a1, a2, a3;
        asm volatile(
            "ldmatrix.sync.aligned.m8n8.x4.trans.shared.b16 {%0,%1,%2,%3}, [%4];"
            : "=r"(a0), "=r"(a1), "=r"(a2), "=r"(a3) : "r"(addr));
#pragma unroll
        for (int nt = 0; nt < 4; ++nt) {
            uint2 bw = *reinterpret_cast<const uint2*>(
                &s_bf[(nt * 4 + kc) * 64 + (lane << 1)]);
            asm volatile(
                "mma.sync.aligned.m16n8k16.row.col.f32.bf16.bf16.f32 "
                "{%0,%1,%2,%3}, {%4,%5,%6,%7}, {%8,%9}, {%0,%1,%2,%3};"
                : "+f"(acc[nt][0]), "+f"(acc[nt][1]),
                  "+f"(acc[nt][2]), "+f"(acc[nt][3])
                : "r"(a0), "r"(a1), "r"(a2), "r"(a3),
                  "r"(bw.x), "r"(bw.y));
        }
    }

    float imp = __ldg(g_imp + b * Tt + t0);
    int eo = (lane & 3) * 2;
    int ep = p0w + (lane >> 2);
    float m_lo = 1.f + s_cv[ep];
    float m_hi = 1.f + s_cv[ep + 8];
#pragma unroll
    for (int nt = 0; nt < 4; ++nt) {
        int o0 = nt * 8 + eo;
        float f0 = sfb[o0], f1 = sfb[o0 + 1];
        s_out[o0 * 132 + ep]            = (acc[nt][0] + f0) * m_lo + imp;
        s_out[(o0 + 1) * 132 + ep]      = (acc[nt][1] + f1) * m_lo + imp;
        s_out[o0 * 132 + ep + 8]        = (acc[nt][2] + f0) * m_hi + imp;
        s_out[(o0 + 1) * 132 + ep + 8]  = (acc[nt][3] + f1) * m_hi + imp;
    }
    __syncthreads();

#pragma unroll
    for (int k = 0; k < 4; ++k) {
        int i = tid + k * 256;
        int o = i >> 5, pq = i & 31;
        float4 v = *reinterpret_cast<const float4*>(&s_out[o * 132 + pq * 4]);
        *reinterpret_cast<float4*>(
            &out[((size_t)(b * Cc + o) * Tt + t0) * Vv + v0 + pq * 4]) = v;
    }
}

// ---------------------------------------------------------------------------
extern "C" void kernel_launch(void* const* d_in, const int* in_sizes, int n_in,
                              void* d_out, int out_size) {
    const float* flow   = (const float*)d_in[0];
    const float* events = (const float*)d_in[1];
    const float* x      = (const float*)d_in[2];
    const float* ef     = (const float*)d_in[3];
    const float* w1     = (const float*)d_in[4];
    const float* b1     = (const float*)d_in[5];
    const float* w2     = (const float*)d_in[6];
    const float* b2     = (const float*)d_in[7];
    const float* fw     = (const float*)d_in[8];
    const float* fb     = (const float*)d_in[9];
    float* out = (float*)d_out;

    const int smem_kF2 = Tt * 32 * sizeof(float);   // 36864 B (cv role max)
    cudaFuncSetAttribute(kF2, cudaFuncAttributeMaxDynamicSharedMemorySize,
                         smem_kF2);

    kF2<<<102, 128, smem_kF2>>>(flow, events, ef, w1, b1, w2, b2, fw);
    kG<<<dim3(Vv / 128, 9, Bc * Cc), 256>>>(x);
    k2t<<<dim3(Vv / 128, Tt, Bc), 256>>>(fb, out);
}